// round 3
// baseline (speedup 1.0000x reference)
#include <cuda_runtime.h>

// img: (1, 64, 64, 1024) float32  -> 64*64*1024 floats
// rois: (1, 1024, 4) int32        -> x, y, w, h
// out: (1, 1024, 7, 7, 1024) float32
//
// One CTA per (roi, cell) where cell = py*7+px. 256 threads each handle 4
// channels via float4. Bilinear: 4 gathers + lerp.

#define POOL 7
#define HW 64
#define C 1024
#define CVEC (C / 4)   // 256 float4 per pixel

__global__ __launch_bounds__(256) void roi_pool_kernel(
    const float* __restrict__ img,
    const int* __restrict__ rois,
    float* __restrict__ out)
{
    const int cell = blockIdx.x;   // 0..48
    const int roi  = blockIdx.y;   // 0..1023
    const int py = cell / POOL;
    const int px = cell % POOL;

    // ROI box
    const int4 r = reinterpret_cast<const int4*>(rois)[roi];
    const int rx = r.x, ry = r.y, rw = r.z, rh = r.w;

    // y axis coords (half-pixel centers, tf.image.resize bilinear)
    float sy   = (float)rh / (float)POOL;
    float srcy = ((float)py + 0.5f) * sy - 0.5f;
    float fy   = floorf(srcy);
    float ty   = srcy - fy;
    int ylo = min(max((int)fy,     0), rh - 1);
    int yhi = min(max((int)fy + 1, 0), rh - 1);
    const int y0 = ry + ylo;
    const int y1 = ry + yhi;

    // x axis coords
    float sx   = (float)rw / (float)POOL;
    float srcx = ((float)px + 0.5f) * sx - 0.5f;
    float fx   = floorf(srcx);
    float tx   = srcx - fx;
    int xlo = min(max((int)fx,     0), rw - 1);
    int xhi = min(max((int)fx + 1, 0), rw - 1);
    const int x0 = rx + xlo;
    const int x1 = rx + xhi;

    // 4 source pixel base pointers (each C contiguous floats)
    const float4* __restrict__ p00 = reinterpret_cast<const float4*>(img + ((size_t)(y0 * HW + x0)) * C);
    const float4* __restrict__ p01 = reinterpret_cast<const float4*>(img + ((size_t)(y0 * HW + x1)) * C);
    const float4* __restrict__ p10 = reinterpret_cast<const float4*>(img + ((size_t)(y1 * HW + x0)) * C);
    const float4* __restrict__ p11 = reinterpret_cast<const float4*>(img + ((size_t)(y1 * HW + x1)) * C);

    float4* __restrict__ o = reinterpret_cast<float4*>(out) + ((size_t)roi * (POOL * POOL) + cell) * CVEC;

    const float wtx  = tx;
    const float wmtx = 1.0f - tx;
    const float wty  = ty;
    const float wmty = 1.0f - ty;

    const int c = threadIdx.x;  // 0..255 float4 lane

    float4 a = p00[c];
    float4 b = p01[c];
    float4 d = p10[c];
    float4 e = p11[c];

    float4 res;
    {
        float top_x = a.x * wmtx + b.x * wtx;
        float bot_x = d.x * wmtx + e.x * wtx;
        res.x = top_x * wmty + bot_x * wty;
        float top_y = a.y * wmtx + b.y * wtx;
        float bot_y = d.y * wmtx + e.y * wtx;
        res.y = top_y * wmty + bot_y * wty;
        float top_z = a.z * wmtx + b.z * wtx;
        float bot_z = d.z * wmtx + e.z * wtx;
        res.z = top_z * wmty + bot_z * wty;
        float top_w = a.w * wmtx + b.w * wtx;
        float bot_w = d.w * wmtx + e.w * wtx;
        res.w = top_w * wmty + bot_w * wty;
    }

    o[c] = res;
}

extern "C" void kernel_launch(void* const* d_in, const int* in_sizes, int n_in,
                              void* d_out, int out_size)
{
    const float* img  = (const float*)d_in[0];
    const int*   rois = (const int*)d_in[1];
    float*       out  = (float*)d_out;

    dim3 grid(POOL * POOL, 1024);
    roi_pool_kernel<<<grid, 256>>>(img, rois, out);
}